// round 15
// baseline (speedup 1.0000x reference)
#include <cuda_runtime.h>
#include <math.h>

#define TN     512
#define TRANGE 8.0f                              // table covers x0 in [-8, 8)
#define TSCALE ((float)TN / (2.0f * TRANGE))     // 32
#define TOFFS  ((float)(TN / 2))                 // 256
#define TINV   (1.0f / TSCALE)

#define RPC    256                               // rows per chunk (= blockDim)
#define F4PC   (RPC * 18 / 4)                    // float4 per chunk = 1152

#define MAGIC  8388608.0f                        // 2^23 RN round trick
#define PI_F   3.14159265358979f

// Constant weights: [0:4) w_ih' [4:8) w_hh' [8:12) bias' (i,f,o pre-scaled 0.5)
// [12:30) w_lin  [30] b_lin  [31:41) odd tanh-poly coeffs b1,b3,...,b19 on [-3,3]
__constant__ float c_w[41];

__device__ float  g_stage[41];
__device__ float4 g_tab[TN];   // (h0, c0, dh, dc): centered-interp step0 table

__device__ __forceinline__ float tanh_fast(float x) {
    float y;
    asm("tanh.approx.f32 %0, %1;" : "=f"(y) : "f"(x));
    return y;
}
__device__ __forceinline__ float sigmoid_pre(float half_x) {
    return fmaf(tanh_fast(half_x), 0.5f, 0.5f);
}

// odd polynomial tanh on [-3,3]; coeffs fitted at runtime (c_w[31..40])
__device__ __forceinline__ float tanh_poly(float c) {
    float t = c * c;
    float p = c_w[40];
    p = fmaf(p, t, c_w[39]);
    p = fmaf(p, t, c_w[38]);
    p = fmaf(p, t, c_w[37]);
    p = fmaf(p, t, c_w[36]);
    p = fmaf(p, t, c_w[35]);
    p = fmaf(p, t, c_w[34]);
    p = fmaf(p, t, c_w[33]);
    p = fmaf(p, t, c_w[32]);
    p = fmaf(p, t, c_w[31]);
    return p * c;
}

// ---------------- setup ----------------------------------------------------
__device__ __forceinline__ void step0_exact(
    float x, float wi, float wg, float wo, float bi, float bg, float bo,
    float* h0, float* c0)
{
    float i0 = 1.0f / (1.0f + expf(-(fmaf(wi, x, bi))));
    float g0 = tanhf(fmaf(wg, x, bg));
    float o0 = 1.0f / (1.0f + expf(-(fmaf(wo, x, bo))));
    float c  = i0 * g0;
    *c0 = c;
    *h0 = o0 * tanhf(c);
}

__global__ void setup_kernel(const float* __restrict__ w_ih,
                             const float* __restrict__ w_hh,
                             const float* __restrict__ b_ih,
                             const float* __restrict__ b_hh,
                             const float* __restrict__ w_lin,
                             const float* __restrict__ b_lin)
{
    __shared__ float fk[64];   // tanh(3 cos th_k) at Chebyshev nodes
    __shared__ float cs[10];   // odd Chebyshev coeffs c1,c3,...,c19

    int t = threadIdx.x;
    if (t < 4) {
        float s = (t == 2) ? 1.0f : 0.5f;       // g gate unscaled
        g_stage[t]     = w_ih[t] * s;
        g_stage[4 + t] = w_hh[t] * s;
        g_stage[8 + t] = (b_ih[t] + b_hh[t]) * s;
    } else if (t < 22) {
        g_stage[8 + t] = w_lin[t - 4];          // 12..29
    } else if (t == 22) {
        g_stage[30] = b_lin[0];
    }

    // ---- step0 table (exact, centered slopes) ----
    const float wi = w_ih[0], wg = w_ih[2], wo = w_ih[3];
    const float bi = b_ih[0] + b_hh[0];
    const float bg = b_ih[2] + b_hh[2];
    const float bo = b_ih[3] + b_hh[3];
    for (int i = t; i < TN; i += blockDim.x) {
        float u = ((float)i - TOFFS) * TINV;
        float h0, c0, hp, cp, hm, cm;
        step0_exact(u,               wi, wg, wo, bi, bg, bo, &h0, &c0);
        step0_exact(u + 0.5f * TINV, wi, wg, wo, bi, bg, bo, &hp, &cp);
        step0_exact(u - 0.5f * TINV, wi, wg, wo, bi, bg, bo, &hm, &cm);
        g_tab[i] = make_float4(h0, c0, hp - hm, cp - cm);
    }

    // ---- runtime Chebyshev fit of tanh on [-3,3], odd degree 19 ----
    if (t < 64) {
        float th = PI_F * ((float)t + 0.5f) / 64.0f;
        fk[t] = tanhf(3.0f * cosf(th));
    }
    __syncthreads();
    if (t < 10) {
        int n = 2 * t + 1;
        float s = 0.0f;
        for (int k = 0; k < 64; k++) {
            float th = PI_F * ((float)k + 0.5f) / 64.0f;
            s += fk[k] * cosf((float)n * th);
        }
        cs[t] = s / 32.0f;   // 2/N with N=64
    }
    __syncthreads();
    if (t == 0) {
        // Chebyshev -> monomial in y (y = c/3), then rescale to c
        float Tm1[20], T0[20], Tn[20], mono[20];
#pragma unroll
        for (int j = 0; j < 20; j++) { Tm1[j] = 0.f; T0[j] = 0.f; mono[j] = 0.f; }
        Tm1[0] = 1.f;           // T0(y)
        T0[1]  = 1.f;           // T1(y)
#pragma unroll
        for (int j = 0; j < 20; j++) mono[j] = cs[0] * T0[j];
#pragma unroll
        for (int n = 2; n <= 19; n++) {
            Tn[0] = -Tm1[0];
#pragma unroll
            for (int j = 1; j < 20; j++) Tn[j] = 2.f * T0[j - 1] - Tm1[j];
            if (n & 1) {
                float cc = cs[n >> 1];
#pragma unroll
                for (int j = 0; j < 20; j++) mono[j] += cc * Tn[j];
            }
#pragma unroll
            for (int j = 0; j < 20; j++) { Tm1[j] = T0[j]; T0[j] = Tn[j]; }
        }
        float p3 = 3.f;
#pragma unroll
        for (int j = 1; j <= 19; j += 2) {
            g_stage[31 + (j >> 1)] = mono[j] / p3;   // b_j = mono_j / 3^j
            p3 *= 9.f;
        }
    }
}

// Steps 1-2 of one element; tanh(c) on fma pipe via tanh_poly.
#define STEPS12(ACC, H, C, X1, X2, WI)                                        \
    do {                                                                      \
        float h_ = (H), c_ = (C);                                             \
        ACC = fmaf(h_, c_w[(WI)], ACC);                                       \
        float i1_ = sigmoid_pre(fmaf(c_w[4], h_, fmaf(c_w[0], (X1), c_w[8])));\
        float f1_ = sigmoid_pre(fmaf(c_w[5], h_, fmaf(c_w[1], (X1), c_w[9])));\
        float g1_ = tanh_fast  (fmaf(c_w[6], h_, fmaf(c_w[2], (X1), c_w[10])));\
        float o1_ = sigmoid_pre(fmaf(c_w[7], h_, fmaf(c_w[3], (X1), c_w[11])));\
        c_ = fmaf(f1_, c_, i1_ * g1_);                                        \
        h_ = o1_ * tanh_poly(c_);                                             \
        ACC = fmaf(h_, c_w[(WI) + 1], ACC);                                   \
        float i2_ = sigmoid_pre(fmaf(c_w[4], h_, fmaf(c_w[0], (X2), c_w[8])));\
        float f2_ = sigmoid_pre(fmaf(c_w[5], h_, fmaf(c_w[1], (X2), c_w[9])));\
        float g2_ = tanh_fast  (fmaf(c_w[6], h_, fmaf(c_w[2], (X2), c_w[10])));\
        float o2_ = sigmoid_pre(fmaf(c_w[7], h_, fmaf(c_w[3], (X2), c_w[11])));\
        c_ = fmaf(f2_, c_, i2_ * g2_);                                        \
        h_ = o2_ * tanh_poly(c_);                                             \
        ACC = fmaf(h_, c_w[(WI) + 2], ACC);                                   \
    } while (0)

// step-0 gather, XU-free (magic-number rounding)
#define STEP0_GATHER(X0, H, C)                                                \
    do {                                                                      \
        float t_ = fmaf((X0), TSCALE, TOFFS);                                 \
        t_ = fminf(fmaxf(t_, 0.0f), (float)(TN - 1));                         \
        float y_  = t_ + MAGIC;                                               \
        int   i_  = __float_as_int(y_) & 0xFFFF;                              \
        float dx_ = t_ - (y_ - MAGIC);                                        \
        float4 e_ = stab[i_];                                                 \
        H = fmaf(dx_, e_.z, e_.x);                                            \
        C = fmaf(dx_, e_.w, e_.y);                                            \
    } while (0)

// ---------------- main kernel: one 256-row chunk per CTA -------------------
__global__ __launch_bounds__(256) void lstm_lin_kernel(
    const float* __restrict__ x, float* __restrict__ out)
{
    __shared__ float4 stab[TN];          // 8 KB step-0 table
    __shared__ float  xs[RPC * 18];      // 18 KB input chunk, linear layout

    const int tid = threadIdx.x;

    stab[tid]       = __ldg(&g_tab[tid]);
    stab[tid + 256] = __ldg(&g_tab[tid + 256]);

    {
        const float4* src = reinterpret_cast<const float4*>(x)
                          + (size_t)blockIdx.x * F4PC;
        float4* xs4 = reinterpret_cast<float4*>(xs);
#pragma unroll
        for (int k = 0; k < 4; k++)
            xs4[tid + 256 * k] = __ldg(src + tid + 256 * k);
        if (tid < F4PC - 1024)
            xs4[tid + 1024] = __ldg(src + tid + 1024);
    }
    __syncthreads();

    // row reads as LDS.64: pitch 18 floats = 9 float2 -> conflict-free per half-warp
    const float2* rp = reinterpret_cast<const float2*>(xs) + tid * 9;

    float acc = c_w[30];
    float h, c;

    float2 q0 = rp[0], q1 = rp[1];
    STEP0_GATHER(q0.x, h, c); STEPS12(acc, h, c, q0.y, q1.x, 12);
    float2 q2 = rp[2];
    STEP0_GATHER(q1.y, h, c); STEPS12(acc, h, c, q2.x, q2.y, 15);
    float2 q3 = rp[3], q4 = rp[4];
    STEP0_GATHER(q3.x, h, c); STEPS12(acc, h, c, q3.y, q4.x, 18);
    float2 q5 = rp[5];
    STEP0_GATHER(q4.y, h, c); STEPS12(acc, h, c, q5.x, q5.y, 21);
    float2 q6 = rp[6], q7 = rp[7];
    STEP0_GATHER(q6.x, h, c); STEPS12(acc, h, c, q6.y, q7.x, 24);
    float2 q8 = rp[8];
    STEP0_GATHER(q7.y, h, c); STEPS12(acc, h, c, q8.x, q8.y, 27);

    out[blockIdx.x * RPC + tid] = acc;
}

extern "C" void kernel_launch(void* const* d_in, const int* in_sizes, int n_in,
                              void* d_out, int out_size)
{
    // Inputs: x, w_ih, w_hh, b_ih, b_hh, w_lin, b_lin
    const float* x = (const float*)d_in[0];

    setup_kernel<<<1, 256>>>((const float*)d_in[1], (const float*)d_in[2],
                             (const float*)d_in[3], (const float*)d_in[4],
                             (const float*)d_in[5], (const float*)d_in[6]);

    void* stage_ptr = nullptr;
    cudaGetSymbolAddress(&stage_ptr, g_stage);
    cudaMemcpyToSymbolAsync(c_w, stage_ptr, 41 * sizeof(float), 0,
                            cudaMemcpyDeviceToDevice, 0);

    int nchunks = out_size / RPC;   // 8192 CTAs, one chunk each
    lstm_lin_kernel<<<nchunks, 256>>>(x, (float*)d_out);
}

// round 16
// speedup vs baseline: 1.1753x; 1.1753x over previous
#include <cuda_runtime.h>
#include <math.h>

#define TN     512
#define TRANGE 8.0f                              // table covers x0 in [-8, 8)
#define TSCALE ((float)TN / (2.0f * TRANGE))     // 32
#define TOFFS  ((float)(TN / 2))                 // 256
#define TINV   (1.0f / TSCALE)

#define RPC    256                               // rows per chunk (= blockDim)
#define F4PC   (RPC * 18 / 4)                    // float4 per chunk = 1152

#define MAGIC  8388608.0f                        // 2^23 RN round trick

// Constant weights (prescaled): [0:4) w_ih' [4:8) w_hh' [8:12) bias'
// (i,f,o gates scaled by 0.5 to fold into sigmoid; g unscaled)
// [12:30) w_lin  [30] b_lin
__constant__ float c_w[31];

__device__ float  g_stage[31];
__device__ float4 g_tab[TN];   // (h0, c0, dh, dc): centered-interp step0 table

__device__ __forceinline__ float tanh_fast(float x) {
    float y;
    asm("tanh.approx.f32 %0, %1;" : "=f"(y) : "f"(x));
    return y;
}
// argument already prescaled by 0.5
__device__ __forceinline__ float sigmoid_pre(float half_x) {
    return fmaf(tanh_fast(half_x), 0.5f, 0.5f);
}

// ---------------- setup: stage weights + build exact step0 table -----------
__device__ __forceinline__ void step0_exact(
    float x, float wi, float wg, float wo, float bi, float bg, float bo,
    float* h0, float* c0)
{
    float i0 = 1.0f / (1.0f + expf(-(fmaf(wi, x, bi))));
    float g0 = tanhf(fmaf(wg, x, bg));
    float o0 = 1.0f / (1.0f + expf(-(fmaf(wo, x, bo))));
    float c  = i0 * g0;
    *c0 = c;
    *h0 = o0 * tanhf(c);
}

__global__ void setup_kernel(const float* __restrict__ w_ih,
                             const float* __restrict__ w_hh,
                             const float* __restrict__ b_ih,
                             const float* __restrict__ b_hh,
                             const float* __restrict__ w_lin,
                             const float* __restrict__ b_lin)
{
    int t = threadIdx.x;
    if (t < 4) {
        float s = (t == 2) ? 1.0f : 0.5f;       // g gate unscaled
        g_stage[t]     = w_ih[t] * s;
        g_stage[4 + t] = w_hh[t] * s;
        g_stage[8 + t] = (b_ih[t] + b_hh[t]) * s;
    } else if (t < 22) {
        g_stage[8 + t] = w_lin[t - 4];          // 12..29
    } else if (t == 22) {
        g_stage[30] = b_lin[0];
    }

    const float wi = w_ih[0], wg = w_ih[2], wo = w_ih[3];
    const float bi = b_ih[0] + b_hh[0];
    const float bg = b_ih[2] + b_hh[2];
    const float bo = b_ih[3] + b_hh[3];

    for (int i = t; i < TN; i += blockDim.x) {
        float u = ((float)i - TOFFS) * TINV;
        float h0, c0, hp, cp, hm, cm;
        step0_exact(u,               wi, wg, wo, bi, bg, bo, &h0, &c0);
        step0_exact(u + 0.5f * TINV, wi, wg, wo, bi, bg, bo, &hp, &cp);
        step0_exact(u - 0.5f * TINV, wi, wg, wo, bi, bg, bo, &hm, &cm);
        // centered interp: F(i+dx) ~ F_i + dx*(F(u+D/2)-F(u-D/2)), dx in [-.5,.5]
        g_tab[i] = make_float4(h0, c0, hp - hm, cp - cm);
    }
}

// Steps 1-2 of one element given (h,c) from the step-0 gather.
#define STEPS12(ACC, H, C, X1, X2, WI)                                        \
    do {                                                                      \
        float h_ = (H), c_ = (C);                                             \
        ACC = fmaf(h_, c_w[(WI)], ACC);                                       \
        float i1_ = sigmoid_pre(fmaf(c_w[4], h_, fmaf(c_w[0], (X1), c_w[8])));\
        float f1_ = sigmoid_pre(fmaf(c_w[5], h_, fmaf(c_w[1], (X1), c_w[9])));\
        float g1_ = tanh_fast  (fmaf(c_w[6], h_, fmaf(c_w[2], (X1), c_w[10])));\
        float o1_ = sigmoid_pre(fmaf(c_w[7], h_, fmaf(c_w[3], (X1), c_w[11])));\
        c_ = fmaf(f1_, c_, i1_ * g1_);                                        \
        h_ = o1_ * tanh_fast(c_);                                             \
        ACC = fmaf(h_, c_w[(WI) + 1], ACC);                                   \
        float i2_ = sigmoid_pre(fmaf(c_w[4], h_, fmaf(c_w[0], (X2), c_w[8])));\
        float f2_ = sigmoid_pre(fmaf(c_w[5], h_, fmaf(c_w[1], (X2), c_w[9])));\
        float g2_ = tanh_fast  (fmaf(c_w[6], h_, fmaf(c_w[2], (X2), c_w[10])));\
        float o2_ = sigmoid_pre(fmaf(c_w[7], h_, fmaf(c_w[3], (X2), c_w[11])));\
        c_ = fmaf(f2_, c_, i2_ * g2_);                                        \
        h_ = o2_ * tanh_fast(c_);                                             \
        ACC = fmaf(h_, c_w[(WI) + 2], ACC);                                   \
    } while (0)

// step-0 gather, XU-free (magic-number rounding, no F2I/I2F)
#define STEP0_GATHER(X0, H, C)                                                \
    do {                                                                      \
        float t_ = fmaf((X0), TSCALE, TOFFS);                                 \
        t_ = fminf(fmaxf(t_, 0.0f), (float)(TN - 1));                         \
        float y_  = t_ + MAGIC;                                               \
        int   i_  = __float_as_int(y_) & 0xFFFF;                              \
        float dx_ = t_ - (y_ - MAGIC);                                        \
        float4 e_ = stab[i_];                                                 \
        H = fmaf(dx_, e_.z, e_.x);                                            \
        C = fmaf(dx_, e_.w, e_.y);                                            \
    } while (0)

// ---------------- main kernel: one 256-row chunk per CTA -------------------
__global__ __launch_bounds__(256) void lstm_lin_kernel(
    const float* __restrict__ x, float* __restrict__ out)
{
    __shared__ float4 stab[TN];          // 8 KB step-0 table
    __shared__ float  xs[RPC * 18];      // 18 KB input chunk, linear layout

    const int tid = threadIdx.x;

    stab[tid]       = __ldg(&g_tab[tid]);
    stab[tid + 256] = __ldg(&g_tab[tid + 256]);

    {
        const float4* src = reinterpret_cast<const float4*>(x)
                          + (size_t)blockIdx.x * F4PC;
        float4* xs4 = reinterpret_cast<float4*>(xs);
#pragma unroll
        for (int k = 0; k < 4; k++)
            xs4[tid + 256 * k] = __ldg(src + tid + 256 * k);
        if (tid < F4PC - 1024)
            xs4[tid + 1024] = __ldg(src + tid + 1024);
    }
    __syncthreads();

    // row reads as LDS.64: pitch-18-float rows = 9 float2 each; banks
    // (9*tid + j) mod 16 distinct per half-warp -> conflict-free
    const float2* rp = reinterpret_cast<const float2*>(xs) + tid * 9;

    float acc = c_w[30];
    float h, c;

    float2 q0 = rp[0], q1 = rp[1];
    STEP0_GATHER(q0.x, h, c); STEPS12(acc, h, c, q0.y, q1.x, 12);
    float2 q2 = rp[2];
    STEP0_GATHER(q1.y, h, c); STEPS12(acc, h, c, q2.x, q2.y, 15);
    float2 q3 = rp[3], q4 = rp[4];
    STEP0_GATHER(q3.x, h, c); STEPS12(acc, h, c, q3.y, q4.x, 18);
    float2 q5 = rp[5];
    STEP0_GATHER(q4.y, h, c); STEPS12(acc, h, c, q5.x, q5.y, 21);
    float2 q6 = rp[6], q7 = rp[7];
    STEP0_GATHER(q6.x, h, c); STEPS12(acc, h, c, q6.y, q7.x, 24);
    float2 q8 = rp[8];
    STEP0_GATHER(q7.y, h, c); STEPS12(acc, h, c, q8.x, q8.y, 27);

    out[blockIdx.x * RPC + tid] = acc;
}

extern "C" void kernel_launch(void* const* d_in, const int* in_sizes, int n_in,
                              void* d_out, int out_size)
{
    // Inputs: x, w_ih, w_hh, b_ih, b_hh, w_lin, b_lin
    const float* x = (const float*)d_in[0];

    setup_kernel<<<1, 256>>>((const float*)d_in[1], (const float*)d_in[2],
                             (const float*)d_in[3], (const float*)d_in[4],
                             (const float*)d_in[5], (const float*)d_in[6]);

    void* stage_ptr = nullptr;
    cudaGetSymbolAddress(&stage_ptr, g_stage);
    cudaMemcpyToSymbolAsync(c_w, stage_ptr, 31 * sizeof(float), 0,
                            cudaMemcpyDeviceToDevice, 0);

    int nchunks = out_size / RPC;   // 8192 CTAs, one chunk each
    lstm_lin_kernel<<<nchunks, 256>>>(x, (float*)d_out);
}

// round 17
// speedup vs baseline: 1.1822x; 1.0059x over previous
#include <cuda_runtime.h>
#include <math.h>

#define TN     256
#define TRANGE 8.0f                              // table covers x0 in [-8, 8)
#define TSCALE ((float)TN / (2.0f * TRANGE))     // 16
#define TOFFS  ((float)(TN / 2))                 // 128
#define TINV   (1.0f / TSCALE)

#define RPC    128                               // rows per chunk (= blockDim)
#define F4PC   (RPC * 18 / 4)                    // float4 per chunk = 576

#define MAGIC  8388608.0f                        // 2^23 RN round trick

// Constant weights (prescaled): [0:4) w_ih' [4:8) w_hh' [8:12) bias'
// (i,f,o gates scaled by 0.5 to fold into sigmoid; g unscaled)
// [12:30) w_lin  [30] b_lin
__constant__ float c_w[31];

__device__ float  g_stage[31];
__device__ float4 g_tab[TN];   // (h0, c0, dh, dc): centered-interp step0 table

__device__ __forceinline__ float tanh_fast(float x) {
    float y;
    asm("tanh.approx.f32 %0, %1;" : "=f"(y) : "f"(x));
    return y;
}
// argument already prescaled by 0.5
__device__ __forceinline__ float sigmoid_pre(float half_x) {
    return fmaf(tanh_fast(half_x), 0.5f, 0.5f);
}

// ---------------- setup: stage weights + build exact step0 table -----------
__device__ __forceinline__ void step0_exact(
    float x, float wi, float wg, float wo, float bi, float bg, float bo,
    float* h0, float* c0)
{
    float i0 = 1.0f / (1.0f + expf(-(fmaf(wi, x, bi))));
    float g0 = tanhf(fmaf(wg, x, bg));
    float o0 = 1.0f / (1.0f + expf(-(fmaf(wo, x, bo))));
    float c  = i0 * g0;
    *c0 = c;
    *h0 = o0 * tanhf(c);
}

__global__ void setup_kernel(const float* __restrict__ w_ih,
                             const float* __restrict__ w_hh,
                             const float* __restrict__ b_ih,
                             const float* __restrict__ b_hh,
                             const float* __restrict__ w_lin,
                             const float* __restrict__ b_lin)
{
    int t = threadIdx.x;
    if (t < 4) {
        float s = (t == 2) ? 1.0f : 0.5f;       // g gate unscaled
        g_stage[t]     = w_ih[t] * s;
        g_stage[4 + t] = w_hh[t] * s;
        g_stage[8 + t] = (b_ih[t] + b_hh[t]) * s;
    } else if (t < 22) {
        g_stage[8 + t] = w_lin[t - 4];          // 12..29
    } else if (t == 22) {
        g_stage[30] = b_lin[0];
    }

    const float wi = w_ih[0], wg = w_ih[2], wo = w_ih[3];
    const float bi = b_ih[0] + b_hh[0];
    const float bg = b_ih[2] + b_hh[2];
    const float bo = b_ih[3] + b_hh[3];

    for (int i = t; i < TN; i += blockDim.x) {
        float u = ((float)i - TOFFS) * TINV;
        float h0, c0, hp, cp, hm, cm;
        step0_exact(u,               wi, wg, wo, bi, bg, bo, &h0, &c0);
        step0_exact(u + 0.5f * TINV, wi, wg, wo, bi, bg, bo, &hp, &cp);
        step0_exact(u - 0.5f * TINV, wi, wg, wo, bi, bg, bo, &hm, &cm);
        // centered interp: F(i+dx) ~ F_i + dx*(F(u+D/2)-F(u-D/2)), dx in [-.5,.5]
        g_tab[i] = make_float4(h0, c0, hp - hm, cp - cm);
    }
}

// Steps 1-2 of one element given (h,c) from the step-0 gather.
#define STEPS12(ACC, H, C, X1, X2, WI)                                        \
    do {                                                                      \
        float h_ = (H), c_ = (C);                                             \
        ACC = fmaf(h_, c_w[(WI)], ACC);                                       \
        float i1_ = sigmoid_pre(fmaf(c_w[4], h_, fmaf(c_w[0], (X1), c_w[8])));\
        float f1_ = sigmoid_pre(fmaf(c_w[5], h_, fmaf(c_w[1], (X1), c_w[9])));\
        float g1_ = tanh_fast  (fmaf(c_w[6], h_, fmaf(c_w[2], (X1), c_w[10])));\
        float o1_ = sigmoid_pre(fmaf(c_w[7], h_, fmaf(c_w[3], (X1), c_w[11])));\
        c_ = fmaf(f1_, c_, i1_ * g1_);                                        \
        h_ = o1_ * tanh_fast(c_);                                             \
        ACC = fmaf(h_, c_w[(WI) + 1], ACC);                                   \
        float i2_ = sigmoid_pre(fmaf(c_w[4], h_, fmaf(c_w[0], (X2), c_w[8])));\
        float f2_ = sigmoid_pre(fmaf(c_w[5], h_, fmaf(c_w[1], (X2), c_w[9])));\
        float g2_ = tanh_fast  (fmaf(c_w[6], h_, fmaf(c_w[2], (X2), c_w[10])));\
        float o2_ = sigmoid_pre(fmaf(c_w[7], h_, fmaf(c_w[3], (X2), c_w[11])));\
        c_ = fmaf(f2_, c_, i2_ * g2_);                                        \
        h_ = o2_ * tanh_fast(c_);                                             \
        ACC = fmaf(h_, c_w[(WI) + 2], ACC);                                   \
    } while (0)

// step-0 gather, XU-free (magic-number rounding, no F2I/I2F)
#define STEP0_GATHER(X0, H, C)                                                \
    do {                                                                      \
        float t_ = fmaf((X0), TSCALE, TOFFS);                                 \
        t_ = fminf(fmaxf(t_, 0.0f), (float)(TN - 1));                         \
        float y_  = t_ + MAGIC;                                               \
        int   i_  = __float_as_int(y_) & 0xFFFF;                              \
        float dx_ = t_ - (y_ - MAGIC);                                        \
        float4 e_ = stab[i_];                                                 \
        H = fmaf(dx_, e_.z, e_.x);                                            \
        C = fmaf(dx_, e_.w, e_.y);                                            \
    } while (0)

// ---------------- main kernel: one 128-row chunk per 128-thread CTA --------
__global__ __launch_bounds__(128) void lstm_lin_kernel(
    const float* __restrict__ x, float* __restrict__ out)
{
    __shared__ float4 stab[TN];          // 4 KB step-0 table
    __shared__ float  xs[RPC * 18];      // 9 KB input chunk, linear layout

    const int tid = threadIdx.x;

    stab[tid]       = __ldg(&g_tab[tid]);
    stab[tid + 128] = __ldg(&g_tab[tid + 128]);

    {
        const float4* src = reinterpret_cast<const float4*>(x)
                          + (size_t)blockIdx.x * F4PC;
        float4* xs4 = reinterpret_cast<float4*>(xs);
#pragma unroll
        for (int k = 0; k < 4; k++)
            xs4[tid + 128 * k] = __ldg(src + tid + 128 * k);
        if (tid < F4PC - 512)                    // tail: 64 float4
            xs4[tid + 512] = __ldg(src + tid + 512);
    }
    __syncthreads();

    // row reads as LDS.64: pitch-18-float rows = 9 float2 each; banks
    // (9*tid + j) mod 16 distinct per half-warp -> conflict-free
    const float2* rp = reinterpret_cast<const float2*>(xs) + tid * 9;

    float acc = c_w[30];
    float h, c;

    float2 q0 = rp[0], q1 = rp[1];
    STEP0_GATHER(q0.x, h, c); STEPS12(acc, h, c, q0.y, q1.x, 12);
    float2 q2 = rp[2];
    STEP0_GATHER(q1.y, h, c); STEPS12(acc, h, c, q2.x, q2.y, 15);
    float2 q3 = rp[3], q4 = rp[4];
    STEP0_GATHER(q3.x, h, c); STEPS12(acc, h, c, q3.y, q4.x, 18);
    float2 q5 = rp[5];
    STEP0_GATHER(q4.y, h, c); STEPS12(acc, h, c, q5.x, q5.y, 21);
    float2 q6 = rp[6], q7 = rp[7];
    STEP0_GATHER(q6.x, h, c); STEPS12(acc, h, c, q6.y, q7.x, 24);
    float2 q8 = rp[8];
    STEP0_GATHER(q7.y, h, c); STEPS12(acc, h, c, q8.x, q8.y, 27);

    out[blockIdx.x * RPC + tid] = acc;
}

extern "C" void kernel_launch(void* const* d_in, const int* in_sizes, int n_in,
                              void* d_out, int out_size)
{
    // Inputs: x, w_ih, w_hh, b_ih, b_hh, w_lin, b_lin
    const float* x = (const float*)d_in[0];

    setup_kernel<<<1, 256>>>((const float*)d_in[1], (const float*)d_in[2],
                             (const float*)d_in[3], (const float*)d_in[4],
                             (const float*)d_in[5], (const float*)d_in[6]);

    void* stage_ptr = nullptr;
    cudaGetSymbolAddress(&stage_ptr, g_stage);
    cudaMemcpyToSymbolAsync(c_w, stage_ptr, 31 * sizeof(float), 0,
                            cudaMemcpyDeviceToDevice, 0);

    int nchunks = out_size / RPC;   // 16384 CTAs, one 128-row chunk each
    lstm_lin_kernel<<<nchunks, 128>>>(x, (float*)d_out);
}